// round 10
// baseline (speedup 1.0000x reference)
#include <cuda_runtime.h>
#include <math.h>

// SparseMixerMoeRoutingMethod: top-2 routing over 64 experts, sparse-mixer mask.
//
// Persistent-warp + software-pipelined version of the validated R9 kernel:
//   - grid-persistent warps, each processing ~7 tiles (8 tokens) via stride;
//   - per iteration the NEXT tile's 4x LDG.128 are issued before the current
//     tile's compute, hiding DRAM latency under ~400 cycles of register/shfl
//     work; no wave-transition overhead.
// Compute core (unchanged, validated):
//   4 lanes/token, chunk-interleaved ownership (lane sub owns float4 chunks
//   {4k+sub}; expert gj = 16k + 4*sub + r).
//   A) multiset top-2 scan + 2-step group reduce -> m1, m2
//      keep <=> (m-x) <= 0.2*max(|x|,m) <=> x >= m*(m>0 ? 0.8 : 1.25) (exact)
//   B) candidate mask of x >= thr2 (superset of both kept sets)
//   C) sparse gather (~0.6 bits/lane): reload via __ldg (L1-hot),
//      e = ex2((x-m1)*log2e); s1 = sum_{x>=thr1} e -> sel1 = 1/s1;
//      s2 = sum_{x>=thr2} e -> sel2 = ex2((m2-m1)*log2e)/(s2-1)
//   D) fused 2-step shfl reduction {s1,s2,mi1,mi2}; rare m1==m2 tie fallback.
//
// Output: single fp32 buffer, [indices-as-float (2n) | values (2n)].

#define NUM_EXPERTS 64
#define L2E 1.4426950408889634f

__device__ __forceinline__ float ex2(float t) {
    float r;
    asm("ex2.approx.ftz.f32 %0, %1;" : "=f"(r) : "f"(t));
    return r;
}
__device__ __forceinline__ float rcp(float t) {
    float r;
    asm("rcp.approx.ftz.f32 %0, %1;" : "=f"(r) : "f"(t));
    return r;
}

__global__ void __launch_bounds__(256)
sparse_mixer_routing_kernel(const float* __restrict__ logits,
                            float* __restrict__ out,
                            int n_tokens) {
    const int lane  = threadIdx.x & 31;
    const int grp   = lane >> 2;          // 8 token-groups of 4 lanes
    const int sub   = lane & 3;
    const int gwarp = blockIdx.x * (blockDim.x >> 5) + (threadIdx.x >> 5);
    const int nwarp = gridDim.x * (blockDim.x >> 5);
    const int n_tiles = (n_tokens + 7) >> 3;
    const int lane_off = sub << 2;

    int tile = gwarp;
    if (tile >= n_tiles) return;

    // row pointer for token grp of tile t (clamped; lanes stay converged)
    #define TILE_ROW(t) \
        (logits + (size_t)min((t) * 8 + grp, n_tokens - 1) * NUM_EXPERTS)

    // ---- prologue: load first tile ----
    float4 nxt0, nxt1, nxt2, nxt3;
    {
        const float4* r4 = reinterpret_cast<const float4*>(TILE_ROW(tile));
        nxt0 = r4[sub]; nxt1 = r4[4 + sub]; nxt2 = r4[8 + sub]; nxt3 = r4[12 + sub];
    }

    while (tile < n_tiles) {
        const float4 c0 = nxt0, c1 = nxt1, c2 = nxt2, c3 = nxt3;
        const float* rowp = TILE_ROW(tile);     // for L1-hot gather reloads
        const int token = tile * 8 + grp;
        const int next_tile = tile + nwarp;     // warp-uniform

        // ---- issue next tile's loads (latency hidden by compute below) ----
        if (next_tile < n_tiles) {
            const float4* r4 =
                reinterpret_cast<const float4*>(TILE_ROW(next_tile));
            nxt0 = r4[sub]; nxt1 = r4[4 + sub];
            nxt2 = r4[8 + sub]; nxt3 = r4[12 + sub];
        }

        // ---- A: multiset top-2 local scan ----
        float x[16];
        x[0]=c0.x; x[1]=c0.y; x[2]=c0.z;  x[3]=c0.w;
        x[4]=c1.x; x[5]=c1.y; x[6]=c1.z;  x[7]=c1.w;
        x[8]=c2.x; x[9]=c2.y; x[10]=c2.z; x[11]=c2.w;
        x[12]=c3.x;x[13]=c3.y;x[14]=c3.z; x[15]=c3.w;

        float m1 = x[0], m2 = -INFINITY;
        #pragma unroll
        for (int j = 1; j < 16; ++j) {
            m2 = fmaxf(m2, fminf(m1, x[j]));
            m1 = fmaxf(m1, x[j]);
        }
        #pragma unroll
        for (int off = 2; off > 0; off >>= 1) {
            const float om1 = __shfl_xor_sync(0xffffffffu, m1, off);
            const float om2 = __shfl_xor_sync(0xffffffffu, m2, off);
            m2 = fmaxf(fmaxf(m2, om2), fminf(m1, om1));
            m1 = fmaxf(m1, om1);
        }

        // ---- B: candidate mask (x >= thr2; thr2 <= thr1) ----
        const float thr2 = m2 * (m2 > 0.0f ? 0.8f : 1.25f);
        unsigned mask = 0;
        #pragma unroll
        for (int j = 0; j < 16; ++j)
            if (x[j] >= thr2) mask |= (1u << j);
        // x[] dead here (gather + fallback reload via __ldg)

        const float thr1 = m1 * (m1 > 0.0f ? 0.8f : 1.25f);
        const float c1c  = -m1 * L2E;

        // ---- C: sparse gather ----
        float s1 = 0.0f, s2 = 0.0f;
        int mi1 = 127, mi2 = 127;
        while (mask) {
            const int j = __ffs(mask) - 1;
            mask &= mask - 1;
            const int gj = ((j & ~3) << 2) + lane_off + (j & 3);
            const float v = __ldg(rowp + gj);     // L1 hit
            const float e = ex2(fmaf(v, L2E, c1c));
            s2 += e;
            if (v >= thr1) s1 += e;
            if (v == m1) mi1 = min(mi1, gj);
            if (v == m2) mi2 = min(mi2, gj);
        }

        // ---- D: fused group reduction ----
        #pragma unroll
        for (int off = 2; off > 0; off >>= 1) {
            s1 += __shfl_xor_sync(0xffffffffu, s1, off);
            s2 += __shfl_xor_sync(0xffffffffu, s2, off);
            mi1 = min(mi1, __shfl_xor_sync(0xffffffffu, mi1, off));
            mi2 = min(mi2, __shfl_xor_sync(0xffffffffu, mi2, off));
        }

        // ---- rare exact-tie fallback: m1 == m2 ----
        if (__ballot_sync(0xffffffffu, m1 == m2)) {
            int sec = 127;
            #pragma unroll
            for (int j = 0; j < 16; ++j) {
                const int gj = ((j & ~3) << 2) + lane_off + (j & 3);
                const float v = __ldg(rowp + gj); // L1-hot
                if (v == m2 && gj != mi1) sec = min(sec, gj);
            }
            #pragma unroll
            for (int off = 2; off > 0; off >>= 1)
                sec = min(sec, __shfl_xor_sync(0xffffffffu, sec, off));
            if (m1 == m2) mi2 = sec;
        }

        const float sel1 = rcp(s1);
        const float sel2 = ex2(fmaf(m2, L2E, c1c)) * rcp(s2 - 1.0f);

        if (sub == 0 && token < n_tokens) {
            reinterpret_cast<float2*>(out)[token] =
                make_float2((float)mi1, (float)mi2);
            reinterpret_cast<float2*>(out + 2 * (size_t)n_tokens)[token] =
                make_float2(sel1, sel2);
        }

        tile = next_tile;
    }
    #undef TILE_ROW
}

extern "C" void kernel_launch(void* const* d_in, const int* in_sizes, int n_in,
                              void* d_out, int out_size) {
    const float* logits = (const float*)d_in[0];
    const int n_tokens  = in_sizes[0] / NUM_EXPERTS;

    float* out = (float*)d_out;

    const int threads = 256;
    const int blocks  = 148 * 8;   // persistent grid, ~7 tiles per warp
    sparse_mixer_routing_kernel<<<blocks, threads>>>(logits, out, n_tokens);
}

// round 11
// speedup vs baseline: 1.0703x; 1.0703x over previous
#include <cuda_runtime.h>
#include <math.h>

// SparseMixerMoeRoutingMethod: top-2 routing over 64 experts, sparse-mixer mask.
//
// Layout (validated R9 core): 4 lanes/token, 8 tokens/warp, chunk-interleaved
// ownership: lane sub owns float4 chunks {4k+sub}, so each LDG.128
// warp-instruction covers a contiguous 64B band of 8 consecutive rows
// (8 L1 lines/instr). Element j (=4k+r) of lane sub -> expert gj=16k+4sub+r.
//
//   A) multiset top-2 scan (3 FMNMX/elem) + 2-step group reduce -> m1, m2
//      keep <=> (m-x) <= 0.2*max(|x|,m) <=> x >= m*(m>0 ? 0.8 : 1.25) (exact)
//   B) 16-bit candidate mask of x >= thr2 (superset of both kept sets);
//      row registers die here (gather reloads via __ldg, L1-hot).
//   C) sparse gather (~0.6 bits/lane): e = ex2((x-m1)*log2e);
//      s1 = sum_{x>=thr1} e -> sel1 = 1/s1
//      s2 = sum_{x>=thr2} e -> sel2 = ex2((m2-m1)*log2e)/(s2-1)
//      index matches tracked as global-index mins.
//   D) fused 2-step shfl reduction {s1,s2,mi1,mi2}; rare m1==m2 tie fallback.
//
// FULL template: when n_tokens % 8 == 0 (this workload), every tile is full ->
// no clamp, no valid predicate, shorter pre-load dependency chain.
//
// Output: single fp32 buffer, [indices-as-float (2n) | values (2n)].

#define NUM_EXPERTS 64
#define L2E 1.4426950408889634f

__device__ __forceinline__ float ex2(float t) {
    float r;
    asm("ex2.approx.ftz.f32 %0, %1;" : "=f"(r) : "f"(t));
    return r;
}
__device__ __forceinline__ float rcp(float t) {
    float r;
    asm("rcp.approx.ftz.f32 %0, %1;" : "=f"(r) : "f"(t));
    return r;
}

template <bool FULL>
__global__ void __launch_bounds__(128, 16)
sparse_mixer_routing_kernel(const float* __restrict__ logits,
                            float* __restrict__ out,
                            int n_tokens) {
    const int warp  = (blockIdx.x * blockDim.x + threadIdx.x) >> 5;
    const int lane  = threadIdx.x & 31;
    const int grp   = lane >> 2;          // 8 token-groups of 4 lanes
    const int sub   = lane & 3;
    const int token = warp * 8 + grp;
    const int tok_c = FULL ? token : min(token, n_tokens - 1);

    const float* rowp = logits + (size_t)tok_c * NUM_EXPERTS;
    const int lane_off = sub << 2;

    float m1, m2;
    unsigned mask = 0;
    {
        const float4* r4 = reinterpret_cast<const float4*>(rowp);
        float x[16];
        #pragma unroll
        for (int k = 0; k < 4; ++k) {
            const float4 v = r4[k * 4 + sub];   // contiguous 64B band / instr
            x[k*4+0] = v.x; x[k*4+1] = v.y; x[k*4+2] = v.z; x[k*4+3] = v.w;
        }

        // ---- A: multiset top-2 local scan ----
        m1 = x[0]; m2 = -INFINITY;
        #pragma unroll
        for (int j = 1; j < 16; ++j) {
            m2 = fmaxf(m2, fminf(m1, x[j]));
            m1 = fmaxf(m1, x[j]);
        }
        // 4-lane group top-2 reduction (xor 2,1 stay in-group)
        #pragma unroll
        for (int off = 2; off > 0; off >>= 1) {
            const float om1 = __shfl_xor_sync(0xffffffffu, m1, off);
            const float om2 = __shfl_xor_sync(0xffffffffu, m2, off);
            m2 = fmaxf(fmaxf(m2, om2), fminf(m1, om1));
            m1 = fmaxf(m1, om1);
        }

        // ---- B: candidate mask (x >= thr2; thr2 <= thr1) ----
        const float t2 = m2 * (m2 > 0.0f ? 0.8f : 1.25f);
        #pragma unroll
        for (int j = 0; j < 16; ++j)
            if (x[j] >= t2) mask |= (1u << j);
        // x[] dead from here (gather + fallback reload via __ldg).
    }

    const float thr1 = m1 * (m1 > 0.0f ? 0.8f : 1.25f);
    const float c1   = -m1 * L2E;

    // ---- C: sparse gather ----
    float s1 = 0.0f, s2 = 0.0f;
    int mi1 = 127, mi2 = 127;
    while (mask) {
        const int j = __ffs(mask) - 1;
        mask &= mask - 1;
        const int gj = ((j & ~3) << 2) + lane_off + (j & 3);  // expert index
        const float v = __ldg(rowp + gj);    // L1 hit (row just loaded)
        const float e = ex2(fmaf(v, L2E, c1));
        s2 += e;
        if (v >= thr1) s1 += e;
        if (v == m1) mi1 = min(mi1, gj);
        if (v == m2) mi2 = min(mi2, gj);
    }

    // ---- D: fused group reduction: sums + index mins ----
    #pragma unroll
    for (int off = 2; off > 0; off >>= 1) {
        s1 += __shfl_xor_sync(0xffffffffu, s1, off);
        s2 += __shfl_xor_sync(0xffffffffu, s2, off);
        mi1 = min(mi1, __shfl_xor_sync(0xffffffffu, mi1, off));
        mi2 = min(mi2, __shfl_xor_sync(0xffffffffu, mi2, off));
    }

    // ---- rare exact-tie fallback: m1 == m2 -> lowest m2-pos excluding mi1 ----
    if (__ballot_sync(0xffffffffu, m1 == m2)) {
        int sec = 127;
        #pragma unroll
        for (int j = 0; j < 16; ++j) {
            const int gj = ((j & ~3) << 2) + lane_off + (j & 3);
            const float v = __ldg(rowp + gj);   // L1-hot
            if (v == m2 && gj != mi1) sec = min(sec, gj);
        }
        #pragma unroll
        for (int off = 2; off > 0; off >>= 1)
            sec = min(sec, __shfl_xor_sync(0xffffffffu, sec, off));
        if (m1 == m2) mi2 = sec;
    }

    const float sel1 = rcp(s1);
    const float sel2 = ex2(fmaf(m2, L2E, c1)) * rcp(s2 - 1.0f);

    if (sub == 0 && (FULL || token < n_tokens)) {
        reinterpret_cast<float2*>(out)[token] =
            make_float2((float)mi1, (float)mi2);
        reinterpret_cast<float2*>(out + 2 * (size_t)n_tokens)[token] =
            make_float2(sel1, sel2);
    }
}

extern "C" void kernel_launch(void* const* d_in, const int* in_sizes, int n_in,
                              void* d_out, int out_size) {
    const float* logits = (const float*)d_in[0];
    const int n_tokens  = in_sizes[0] / NUM_EXPERTS;

    float* out = (float*)d_out;

    const int threads = 128;                 // 4 warps = 32 tokens/block
    const int tokens_per_block = (threads / 32) * 8;

    if ((n_tokens & 7) == 0) {
        const int blocks = n_tokens / tokens_per_block;
        sparse_mixer_routing_kernel<true><<<blocks, threads>>>(logits, out,
                                                               n_tokens);
    } else {
        const int blocks = (n_tokens + tokens_per_block - 1) / tokens_per_block;
        sparse_mixer_routing_kernel<false><<<blocks, threads>>>(logits, out,
                                                                n_tokens);
    }
}